// round 3
// baseline (speedup 1.0000x reference)
#include <cuda_runtime.h>

#define N_NODES 100000
#define D 128
#define N_EDGES 1600000

// Scratch (__device__ globals per allocation rules)
__device__ float g_Y[(size_t)N_NODES * D];                // x @ W   (51.2 MB)
__device__ int g_cnt[N_NODES];                            // histogram
__device__ int g_start[N_NODES + 1];                      // CSR offsets
__device__ int g_ptr[N_NODES];                            // placement cursors
__device__ unsigned long long g_edge[N_EDGES];            // packed (val:hi32, src:lo32)

// ---------------------------------------------------------------------------
// Counting sort stage 1: zero histogram
// ---------------------------------------------------------------------------
__global__ void __launch_bounds__(256) zero_cnt_kernel() {
    int i = blockIdx.x * 256 + threadIdx.x;
    if (i < N_NODES) g_cnt[i] = 0;
}

// Stage 2: histogram of dst
__global__ void __launch_bounds__(256) hist_kernel(const int* __restrict__ dst) {
    int e = blockIdx.x * 256 + threadIdx.x;
    if (e < N_EDGES) atomicAdd(&g_cnt[dst[e]], 1);
}

// Stage 3: exclusive scan (single block, 1024 threads, ~98 elems/thread)
__global__ void __launch_bounds__(1024) scan_kernel() {
    __shared__ int part[1024];
    const int t = threadIdx.x;
    const int chunk = (N_NODES + 1023) / 1024;   // 98
    const int lo = t * chunk;
    const int hi = min(lo + chunk, N_NODES);

    int s = 0;
    for (int i = lo; i < hi; i++) s += g_cnt[i];
    part[t] = s;
    __syncthreads();

    // Hillis-Steele inclusive scan over 1024 partials
    for (int off = 1; off < 1024; off <<= 1) {
        int v = (t >= off) ? part[t - off] : 0;
        __syncthreads();
        part[t] += v;
        __syncthreads();
    }

    int run = (t == 0) ? 0 : part[t - 1];        // exclusive base for this chunk
    for (int i = lo; i < hi; i++) {
        g_start[i] = run;
        g_ptr[i]   = run;
        run += g_cnt[i];
    }
    if (t == 1023) g_start[N_NODES] = N_EDGES;
}

// Stage 4: place edges into dst-sorted order, packing (val, src)
__global__ void __launch_bounds__(256) place_kernel(const int*   __restrict__ src,
                                                    const int*   __restrict__ dst,
                                                    const float* __restrict__ val) {
    int e = blockIdx.x * 256 + threadIdx.x;
    if (e >= N_EDGES) return;
    int d = dst[e];
    int pos = atomicAdd(&g_ptr[d], 1);
    unsigned long long p =
        ((unsigned long long)__float_as_uint(val[e]) << 32) | (unsigned)src[e];
    g_edge[pos] = p;
}

// ---------------------------------------------------------------------------
// GEMM: Y = x @ W   (x: [N_NODES, 128], W: [128, 128])
// Block = 256 threads, 32 rows per block; warp owns 4 rows, lane owns 4 cols.
// ---------------------------------------------------------------------------
constexpr int BR = 32;

__global__ void __launch_bounds__(256) gemm_kernel(const float* __restrict__ x,
                                                   const float* __restrict__ w) {
    __shared__ float xs[BR][D];
    const int row0 = blockIdx.x * BR;

    const float4* xin = (const float4*)(x + (size_t)row0 * D);
    float4* xs4 = (float4*)xs;
#pragma unroll
    for (int i = 0; i < (BR * D / 4) / 256; i++)
        xs4[threadIdx.x + i * 256] = xin[threadIdx.x + i * 256];
    __syncthreads();

    const int lane = threadIdx.x & 31;
    const int warp = threadIdx.x >> 5;

    float4 acc0 = make_float4(0.f, 0.f, 0.f, 0.f);
    float4 acc1 = acc0, acc2 = acc0, acc3 = acc0;

    const float* x0 = xs[warp];
    const float* x1 = xs[warp + 8];
    const float* x2 = xs[warp + 16];
    const float* x3 = xs[warp + 24];
    const float4* wrow = (const float4*)w + lane;

#pragma unroll 8
    for (int k = 0; k < D; k++) {
        float4 wv = wrow[k * 32];
        float a0 = x0[k], a1 = x1[k], a2 = x2[k], a3 = x3[k];
        acc0.x += a0 * wv.x; acc0.y += a0 * wv.y; acc0.z += a0 * wv.z; acc0.w += a0 * wv.w;
        acc1.x += a1 * wv.x; acc1.y += a1 * wv.y; acc1.z += a1 * wv.z; acc1.w += a1 * wv.w;
        acc2.x += a2 * wv.x; acc2.y += a2 * wv.y; acc2.z += a2 * wv.z; acc2.w += a2 * wv.w;
        acc3.x += a3 * wv.x; acc3.y += a3 * wv.y; acc3.z += a3 * wv.z; acc3.w += a3 * wv.w;
    }

    float4* yout = (float4*)g_Y;
    yout[(size_t)(row0 + warp)      * 32 + lane] = acc0;
    yout[(size_t)(row0 + warp + 8)  * 32 + lane] = acc1;
    yout[(size_t)(row0 + warp + 16) * 32 + lane] = acc2;
    yout[(size_t)(row0 + warp + 24) * 32 + lane] = acc3;
}

// ---------------------------------------------------------------------------
// Gather: one warp per dst node. Register-accumulate 128 floats (4 per lane),
// single plain float4 store. No atomics, no zero pass.
// Software-pipelined edge fetch to overlap packed-edge load with Y gather.
// ---------------------------------------------------------------------------
__global__ void __launch_bounds__(256) gather_kernel(float* __restrict__ z) {
    const int node = blockIdx.x * 8 + (threadIdx.x >> 5);
    const int lane = threadIdx.x & 31;

    const int beg = g_start[node];
    const int end = g_start[node + 1];

    float4 acc = make_float4(0.f, 0.f, 0.f, 0.f);
    const float4* Y4 = (const float4*)g_Y;

    if (beg < end) {
        unsigned long long p = __ldg(&g_edge[beg]);
        for (int i = beg; i < end; i++) {
            const int   s = (int)(p & 0xffffffffu);
            const float v = __uint_as_float((unsigned)(p >> 32));
            if (i + 1 < end) p = __ldg(&g_edge[i + 1]);   // prefetch next edge
            float4 m = Y4[(size_t)s * 32 + lane];
            acc.x += v * m.x; acc.y += v * m.y;
            acc.z += v * m.z; acc.w += v * m.w;
        }
    }
    ((float4*)z)[(size_t)node * 32 + lane] = acc;
}

// ---------------------------------------------------------------------------
// Launch
// ---------------------------------------------------------------------------
extern "C" void kernel_launch(void* const* d_in, const int* in_sizes, int n_in,
                              void* d_out, int out_size) {
    const float* x   = (const float*)d_in[0];
    const float* w   = (const float*)d_in[1];
    const int*   src = (const int*)  d_in[2];
    const int*   dst = (const int*)  d_in[3];
    const float* val = (const float*)d_in[4];
    float*       z   = (float*)d_out;

    zero_cnt_kernel<<<(N_NODES + 255) / 256, 256>>>();
    hist_kernel<<<(N_EDGES + 255) / 256, 256>>>(dst);
    scan_kernel<<<1, 1024>>>();
    place_kernel<<<(N_EDGES + 255) / 256, 256>>>(src, dst, val);
    gemm_kernel<<<N_NODES / BR, 256>>>(x, w);
    gather_kernel<<<N_NODES / 8, 256>>>(z);
}